// round 6
// baseline (speedup 1.0000x reference)
#include <cuda_runtime.h>
#include <cuda_bf16.h>
#include <cstdint>
#include <cstddef>

#define D 128
#define MAXN 50000
#define MAXE 600064
#define SCAN_B 256
#define MAXNB ((MAXN + SCAN_B - 1) / SCAN_B)   // 196

// ---- scratch (allocation-free: __device__ globals) ----
__device__ int   g_cnt_out[MAXN];
__device__ int   g_cnt_in[MAXN];
__device__ float g_norm_src[MAXN];
__device__ float g_norm_dst[MAXN];
__device__ int   g_row_start[MAXN];
__device__ int   g_cursor[MAXN];
__device__ int   g_blk_sums[SCAN_B];
__device__ int   g_sorted_src[MAXE];
__device__ float g_h[(size_t)MAXN * D];        // layer-1 output

__global__ void k_zero2i(int* a, int* b, int n) {
    int i = blockIdx.x * blockDim.x + threadIdx.x;
    if (i < n) { a[i] = 0; b[i] = 0; }
}

__global__ void k_hist(const int* __restrict__ src, const int* __restrict__ dst,
                       int* __restrict__ cnt_out, int* __restrict__ cnt_in, int E) {
    int i = blockIdx.x * blockDim.x + threadIdx.x;
    if (i < E) {
        atomicAdd(&cnt_out[src[i]], 1);
        atomicAdd(&cnt_in[dst[i]], 1);
    }
}

// ---- block-level exclusive scan of cnt_in ----
__global__ void k_scan_block(const int* __restrict__ cnt, int* __restrict__ excl,
                             int* __restrict__ blk_sums, int N) {
    __shared__ int sh[SCAN_B];
    int i = blockIdx.x * SCAN_B + threadIdx.x;
    int v = (i < N) ? cnt[i] : 0;
    sh[threadIdx.x] = v; __syncthreads();
#pragma unroll
    for (int off = 1; off < SCAN_B; off <<= 1) {
        int t = (threadIdx.x >= off) ? sh[threadIdx.x - off] : 0;
        __syncthreads();
        sh[threadIdx.x] += t;
        __syncthreads();
    }
    if (i < N) excl[i] = sh[threadIdx.x] - v;
    if (threadIdx.x == SCAN_B - 1) blk_sums[blockIdx.x] = sh[SCAN_B - 1];
}

// ---- finish scan (each block reduces its own prefix over blk_sums) + norms ----
__global__ void k_scan_add_norm(int* __restrict__ excl, const int* __restrict__ blk_sums,
                                int* __restrict__ cursor,
                                const int* __restrict__ cnt_out, const int* __restrict__ cnt_in,
                                float* __restrict__ nsrc, float* __restrict__ ndst,
                                int nb, int N) {
    __shared__ int sh[SCAN_B];
    // reduce blk_sums[0 .. blockIdx.x) with 256 threads
    int v = (threadIdx.x < blockIdx.x && threadIdx.x < nb) ? blk_sums[threadIdx.x] : 0;
    sh[threadIdx.x] = v; __syncthreads();
#pragma unroll
    for (int off = 128; off > 0; off >>= 1) {
        if (threadIdx.x < off) sh[threadIdx.x] += sh[threadIdx.x + off];
        __syncthreads();
    }
    int prefix = sh[0];
    int i = blockIdx.x * SCAN_B + threadIdx.x;
    if (i < N) {
        int r = excl[i] + prefix;
        excl[i] = r;
        cursor[i] = r;
        nsrc[i] = rsqrtf(fmaxf((float)cnt_out[i], 1.f));
        ndst[i] = rsqrtf(fmaxf((float)cnt_in[i], 1.f));
    }
}

// ---- bucket edges by dst: CSR src list ----
__global__ void k_bucket(const int* __restrict__ src, const int* __restrict__ dst,
                         int* __restrict__ cursor, int* __restrict__ sorted_src, int E) {
    int i = blockIdx.x * blockDim.x + threadIdx.x;
    if (i < E) {
        int pos = atomicAdd(&cursor[dst[i]], 1);
        sorted_src[pos] = src[i];
    }
}

// ---- tf32 helpers ----
__device__ __forceinline__ uint32_t f2tf32(float x) {
    uint32_t r;
    asm("cvt.rna.tf32.f32 %0, %1;" : "=r"(r) : "f"(x));
    return r;
}

__device__ __forceinline__ void mma_tf32(float* c, uint32_t a0, uint32_t a1,
                                         uint32_t a2, uint32_t a3,
                                         uint32_t b0, uint32_t b1) {
    asm volatile(
        "mma.sync.aligned.m16n8k8.row.col.f32.tf32.tf32.f32 "
        "{%0,%1,%2,%3}, {%4,%5,%6,%7}, {%8,%9}, {%0,%1,%2,%3};"
        : "+f"(c[0]), "+f"(c[1]), "+f"(c[2]), "+f"(c[3])
        : "r"(a0), "r"(a1), "r"(a2), "r"(a3), "r"(b0), "r"(b1));
}

// ---- fused layer: gather(CSR) -> SMEM -> tf32 GEMM -> bias+relu ----
// block = 256 threads (8 warps), tile = 128 dst rows x 128 cols.
#define ASF_STRIDE 132   // full 128-col A tile; bank = (4*row + col) % 32
#define WS_STRIDE 136

__global__ __launch_bounds__(256)
void k_layer(const float* __restrict__ h, const int* __restrict__ sorted_src,
             const int* __restrict__ row_start, const int* __restrict__ cnt_in,
             const float* __restrict__ nsrc, const float* __restrict__ ndst,
             const float* __restrict__ Wm, const float* __restrict__ bias,
             float* __restrict__ C, int N) {
    extern __shared__ uint32_t sh[];
    uint32_t* As = sh;                          // 128 x ASF_STRIDE (tf32)
    uint32_t* Ws = sh + 128 * ASF_STRIDE;       // 32 x WS_STRIDE (tf32)

    const int tid = threadIdx.x;
    const int warp = tid >> 5;
    const int lane = tid & 31;
    const int g = lane >> 2;
    const int t = lane & 3;
    const int row0 = blockIdx.x * 128;

    // ---- gather phase: warp per dst row, 16 rows per warp ----
    for (int rr = warp; rr < 128; rr += 8) {
        int n = row0 + rr;
        float4 acc = make_float4(0.f, 0.f, 0.f, 0.f);
        if (n < N) {
            int start = __ldg(&row_start[n]);
            int cnt = __ldg(&cnt_in[n]);
            int j = 0;
            for (; j + 2 <= cnt; j += 2) {
                int s0 = __ldg(&sorted_src[start + j]);
                int s1 = __ldg(&sorted_src[start + j + 1]);
                float ns0 = __ldg(&nsrc[s0]);
                float ns1 = __ldg(&nsrc[s1]);
                float4 v0 = __ldg((const float4*)(h + (size_t)s0 * D) + lane);
                float4 v1 = __ldg((const float4*)(h + (size_t)s1 * D) + lane);
                acc.x = fmaf(ns0, v0.x, acc.x); acc.y = fmaf(ns0, v0.y, acc.y);
                acc.z = fmaf(ns0, v0.z, acc.z); acc.w = fmaf(ns0, v0.w, acc.w);
                acc.x = fmaf(ns1, v1.x, acc.x); acc.y = fmaf(ns1, v1.y, acc.y);
                acc.z = fmaf(ns1, v1.z, acc.z); acc.w = fmaf(ns1, v1.w, acc.w);
            }
            if (j < cnt) {
                int s = __ldg(&sorted_src[start + j]);
                float ns = __ldg(&nsrc[s]);
                float4 v = __ldg((const float4*)(h + (size_t)s * D) + lane);
                acc.x = fmaf(ns, v.x, acc.x); acc.y = fmaf(ns, v.y, acc.y);
                acc.z = fmaf(ns, v.z, acc.z); acc.w = fmaf(ns, v.w, acc.w);
            }
            float nd = __ldg(&ndst[n]);
            acc.x *= nd; acc.y *= nd; acc.z *= nd; acc.w *= nd;
        }
        uint32_t* p = &As[rr * ASF_STRIDE + lane * 4];
        p[0] = f2tf32(acc.x); p[1] = f2tf32(acc.y);
        p[2] = f2tf32(acc.z); p[3] = f2tf32(acc.w);
    }
    __syncthreads();

    // ---- MMA phase ----
    float acc[16][4];
#pragma unroll
    for (int j = 0; j < 16; j++)
#pragma unroll
        for (int i = 0; i < 4; i++) acc[j][i] = 0.f;

    for (int kt = 0; kt < 128; kt += 32) {
        // stage W k-tile [32][128] -> Ws (tf32)
#pragma unroll
        for (int j = 0; j < 4; j++) {
            int f = tid + j * 256;
            int kk = f >> 5;
            int c4 = f & 31;
            float4 w = __ldg((const float4*)&Wm[(size_t)(kt + kk) * 128 + c4 * 4]);
            uint32_t* p = &Ws[kk * WS_STRIDE + c4 * 4];
            p[0] = f2tf32(w.x); p[1] = f2tf32(w.y); p[2] = f2tf32(w.z); p[3] = f2tf32(w.w);
        }
        __syncthreads();

#pragma unroll
        for (int k8 = 0; k8 < 4; k8++) {
            int kb = k8 * 8;
            int r = warp * 16;
            uint32_t a0 = As[(r + g) * ASF_STRIDE + kt + kb + t];
            uint32_t a1 = As[(r + g + 8) * ASF_STRIDE + kt + kb + t];
            uint32_t a2 = As[(r + g) * ASF_STRIDE + kt + kb + t + 4];
            uint32_t a3 = As[(r + g + 8) * ASF_STRIDE + kt + kb + t + 4];
#pragma unroll
            for (int j = 0; j < 16; j++) {
                uint32_t b0 = Ws[(kb + t) * WS_STRIDE + j * 8 + g];
                uint32_t b1 = Ws[(kb + t + 4) * WS_STRIDE + j * 8 + g];
                mma_tf32(acc[j], a0, a1, a2, a3, b0, b1);
            }
        }
        __syncthreads();
    }

    // ---- epilogue: bias + relu ----
    const int r1 = row0 + warp * 16 + g;
    const int r2 = r1 + 8;
#pragma unroll
    for (int j = 0; j < 16; j++) {
        int col = j * 8 + 2 * t;
        float2 bv = *(const float2*)&bias[col];
        if (r1 < N) {
            float2 o;
            o.x = fmaxf(acc[j][0] + bv.x, 0.f);
            o.y = fmaxf(acc[j][1] + bv.y, 0.f);
            *(float2*)&C[(size_t)r1 * 128 + col] = o;
        }
        if (r2 < N) {
            float2 o;
            o.x = fmaxf(acc[j][2] + bv.x, 0.f);
            o.y = fmaxf(acc[j][3] + bv.y, 0.f);
            *(float2*)&C[(size_t)r2 * 128 + col] = o;
        }
    }
}

#define LAYER_SMEM ((128 * ASF_STRIDE + 32 * WS_STRIDE) * 4)

extern "C" void kernel_launch(void* const* d_in, const int* in_sizes, int n_in,
                              void* d_out, int out_size) {
    const float* features = (const float*)d_in[0];
    const int* src = (const int*)d_in[1];
    const int* dst = (const int*)d_in[2];
    const float* W1 = (const float*)d_in[3];
    const float* b1 = (const float*)d_in[4];
    const float* W2 = (const float*)d_in[5];
    const float* b2 = (const float*)d_in[6];
    float* out = (float*)d_out;

    int N = in_sizes[0] / D;
    int E = in_sizes[1];

    int *cnt_out, *cnt_in, *row_start, *cursor, *blk_sums, *sorted_src;
    float *nsrc, *ndst, *h1;
    cudaGetSymbolAddress((void**)&cnt_out, g_cnt_out);
    cudaGetSymbolAddress((void**)&cnt_in, g_cnt_in);
    cudaGetSymbolAddress((void**)&row_start, g_row_start);
    cudaGetSymbolAddress((void**)&cursor, g_cursor);
    cudaGetSymbolAddress((void**)&blk_sums, g_blk_sums);
    cudaGetSymbolAddress((void**)&sorted_src, g_sorted_src);
    cudaGetSymbolAddress((void**)&nsrc, g_norm_src);
    cudaGetSymbolAddress((void**)&ndst, g_norm_dst);
    cudaGetSymbolAddress((void**)&h1, g_h);

    static bool attr_set = false;
    if (!attr_set) {
        cudaFuncSetAttribute(k_layer, cudaFuncAttributeMaxDynamicSharedMemorySize, LAYER_SMEM);
        attr_set = true;
    }

    const int ZB = 256;
    int nblkN = (N + ZB - 1) / ZB;
    int nblkE = (E + ZB - 1) / ZB;

    // CSR build + norms (5 launches)
    k_zero2i<<<nblkN, ZB>>>(cnt_out, cnt_in, N);
    k_hist<<<nblkE, ZB>>>(src, dst, cnt_out, cnt_in, E);
    k_scan_block<<<nblkN, SCAN_B>>>(cnt_in, row_start, blk_sums, N);
    k_scan_add_norm<<<nblkN, SCAN_B>>>(row_start, blk_sums, cursor,
                                       cnt_out, cnt_in, nsrc, ndst, nblkN, N);
    k_bucket<<<nblkE, ZB>>>(src, dst, cursor, sorted_src, E);

    int layer_blocks = (N + 127) / 128;

    // fused layers
    k_layer<<<layer_blocks, 256, LAYER_SMEM>>>(features, sorted_src, row_start, cnt_in,
                                               nsrc, ndst, W1, b1, h1, N);
    k_layer<<<layer_blocks, 256, LAYER_SMEM>>>(h1, sorted_src, row_start, cnt_in,
                                               nsrc, ndst, W2, b2, out, N);
}

// round 7
// speedup vs baseline: 1.3088x; 1.3088x over previous
#include <cuda_runtime.h>
#include <cuda_fp16.h>
#include <cstdint>
#include <cstddef>

#define D 128
#define MAXN 50000
#define MAXE 600064
#define SCAN_B 256

// ---- scratch (allocation-free: __device__ globals) ----
__device__ int    g_cnt_out[MAXN];
__device__ int    g_cnt_in[MAXN];
__device__ float  g_norm_src[MAXN];
__device__ float  g_norm_dst[MAXN];
__device__ int    g_row_start[MAXN];
__device__ int    g_cursor[MAXN];
__device__ int    g_blk_sums[SCAN_B];
__device__ int    g_sorted_src[MAXE];
__device__ __half g_hf16[(size_t)MAXN * D];    // fp16 mirror of gather operand
__device__ float  g_agg[(size_t)MAXN * D];     // aggregation buffer (fp32)

__global__ void k_zero2i(int* a, int* b, int n) {
    int i = blockIdx.x * blockDim.x + threadIdx.x;
    if (i < n) { a[i] = 0; b[i] = 0; }
}

__global__ void k_hist(const int* __restrict__ src, const int* __restrict__ dst,
                       int* __restrict__ cnt_out, int* __restrict__ cnt_in, int E) {
    int i = blockIdx.x * blockDim.x + threadIdx.x;
    if (i < E) {
        atomicAdd(&cnt_out[src[i]], 1);
        atomicAdd(&cnt_in[dst[i]], 1);
    }
}

// ---- fp32 -> fp16 conversion (features mirror), 4 elems/thread ----
__global__ void k_f2h(const float* __restrict__ in, __half* __restrict__ out, int n4) {
    int i = blockIdx.x * blockDim.x + threadIdx.x;
    if (i < n4) {
        float4 v = __ldg((const float4*)in + i);
        __half2 h0 = __floats2half2_rn(v.x, v.y);
        __half2 h1 = __floats2half2_rn(v.z, v.w);
        uint2 u;
        u.x = *(uint32_t*)&h0;
        u.y = *(uint32_t*)&h1;
        *((uint2*)out + i) = u;
    }
}

// ---- block-level exclusive scan of cnt_in ----
__global__ void k_scan_block(const int* __restrict__ cnt, int* __restrict__ excl,
                             int* __restrict__ blk_sums, int N) {
    __shared__ int sh[SCAN_B];
    int i = blockIdx.x * SCAN_B + threadIdx.x;
    int v = (i < N) ? cnt[i] : 0;
    sh[threadIdx.x] = v; __syncthreads();
#pragma unroll
    for (int off = 1; off < SCAN_B; off <<= 1) {
        int t = (threadIdx.x >= off) ? sh[threadIdx.x - off] : 0;
        __syncthreads();
        sh[threadIdx.x] += t;
        __syncthreads();
    }
    if (i < N) excl[i] = sh[threadIdx.x] - v;
    if (threadIdx.x == SCAN_B - 1) blk_sums[blockIdx.x] = sh[SCAN_B - 1];
}

// ---- finish scan (per-block prefix reduce) + norms ----
__global__ void k_scan_add_norm(int* __restrict__ excl, const int* __restrict__ blk_sums,
                                int* __restrict__ cursor,
                                const int* __restrict__ cnt_out, const int* __restrict__ cnt_in,
                                float* __restrict__ nsrc, float* __restrict__ ndst,
                                int nb, int N) {
    __shared__ int sh[SCAN_B];
    int v = (threadIdx.x < blockIdx.x && threadIdx.x < nb) ? blk_sums[threadIdx.x] : 0;
    sh[threadIdx.x] = v; __syncthreads();
#pragma unroll
    for (int off = 128; off > 0; off >>= 1) {
        if (threadIdx.x < off) sh[threadIdx.x] += sh[threadIdx.x + off];
        __syncthreads();
    }
    int prefix = sh[0];
    int i = blockIdx.x * SCAN_B + threadIdx.x;
    if (i < N) {
        int r = excl[i] + prefix;
        excl[i] = r;
        cursor[i] = r;
        nsrc[i] = rsqrtf(fmaxf((float)cnt_out[i], 1.f));
        ndst[i] = rsqrtf(fmaxf((float)cnt_in[i], 1.f));
    }
}

// ---- bucket edges by dst: CSR src list ----
__global__ void k_bucket(const int* __restrict__ src, const int* __restrict__ dst,
                         int* __restrict__ cursor, int* __restrict__ sorted_src, int E) {
    int i = blockIdx.x * blockDim.x + threadIdx.x;
    if (i < E) {
        int pos = atomicAdd(&cursor[dst[i]], 1);
        sorted_src[pos] = src[i];
    }
}

// ---- atomic-free aggregation from fp16 rows: warp per dst node ----
// lane handles 4 consecutive halves (8 bytes); accumulate fp32.
__global__ void k_gather16(const __half* __restrict__ hf, const int* __restrict__ sorted_src,
                           const int* __restrict__ row_start, const int* __restrict__ cnt_in,
                           const float* __restrict__ nsrc, float* __restrict__ agg, int N) {
    int n = (blockIdx.x * blockDim.x + threadIdx.x) >> 5;
    int lane = threadIdx.x & 31;
    if (n >= N) return;
    int start = __ldg(&row_start[n]);
    int cnt = __ldg(&cnt_in[n]);
    float4 acc = make_float4(0.f, 0.f, 0.f, 0.f);
    int j = 0;
    for (; j + 2 <= cnt; j += 2) {
        int s0 = __ldg(&sorted_src[start + j]);
        int s1 = __ldg(&sorted_src[start + j + 1]);
        float ns0 = __ldg(&nsrc[s0]);
        float ns1 = __ldg(&nsrc[s1]);
        uint2 u0 = __ldg((const uint2*)(hf + (size_t)s0 * D) + lane);
        uint2 u1 = __ldg((const uint2*)(hf + (size_t)s1 * D) + lane);
        float2 a0 = __half22float2(*(__half2*)&u0.x);
        float2 b0 = __half22float2(*(__half2*)&u0.y);
        float2 a1 = __half22float2(*(__half2*)&u1.x);
        float2 b1 = __half22float2(*(__half2*)&u1.y);
        acc.x = fmaf(ns0, a0.x, acc.x); acc.y = fmaf(ns0, a0.y, acc.y);
        acc.z = fmaf(ns0, b0.x, acc.z); acc.w = fmaf(ns0, b0.y, acc.w);
        acc.x = fmaf(ns1, a1.x, acc.x); acc.y = fmaf(ns1, a1.y, acc.y);
        acc.z = fmaf(ns1, b1.x, acc.z); acc.w = fmaf(ns1, b1.y, acc.w);
    }
    if (j < cnt) {
        int s = __ldg(&sorted_src[start + j]);
        float ns = __ldg(&nsrc[s]);
        uint2 u = __ldg((const uint2*)(hf + (size_t)s * D) + lane);
        float2 a = __half22float2(*(__half2*)&u.x);
        float2 b = __half22float2(*(__half2*)&u.y);
        acc.x = fmaf(ns, a.x, acc.x); acc.y = fmaf(ns, a.y, acc.y);
        acc.z = fmaf(ns, b.x, acc.z); acc.w = fmaf(ns, b.y, acc.w);
    }
    *((float4*)(agg + (size_t)n * D) + lane) = acc;
}

// ---- tf32 helpers ----
__device__ __forceinline__ uint32_t f2tf32(float x) {
    uint32_t r;
    asm("cvt.rna.tf32.f32 %0, %1;" : "=r"(r) : "f"(x));
    return r;
}

__device__ __forceinline__ void mma_tf32(float* c, uint32_t a0, uint32_t a1,
                                         uint32_t a2, uint32_t a3,
                                         uint32_t b0, uint32_t b1) {
    asm volatile(
        "mma.sync.aligned.m16n8k8.row.col.f32.tf32.tf32.f32 "
        "{%0,%1,%2,%3}, {%4,%5,%6,%7}, {%8,%9}, {%0,%1,%2,%3};"
        : "+f"(c[0]), "+f"(c[1]), "+f"(c[2]), "+f"(c[3])
        : "r"(a0), "r"(a1), "r"(a2), "r"(a3), "r"(b0), "r"(b1));
}

// ---- fused: C = relu((A * norm[:,None]) @ W + b) -> fp32 and/or fp16 out ----
#define AS_STRIDE 36
#define WS_STRIDE 136

template <bool HALF_OUT>
__global__ __launch_bounds__(256)
void k_gemm_tf32(const float* __restrict__ A, const float* __restrict__ Wm,
                 const float* __restrict__ bias, const float* __restrict__ norm,
                 float* __restrict__ C, __half* __restrict__ C16, int N) {
    __shared__ uint32_t As[128 * AS_STRIDE];
    __shared__ uint32_t Ws[32 * WS_STRIDE];

    const int tid = threadIdx.x;
    const int warp = tid >> 5;
    const int lane = tid & 31;
    const int g = lane >> 2;
    const int t = lane & 3;
    const int row0 = blockIdx.x * 128;

    float acc[16][4];
#pragma unroll
    for (int j = 0; j < 16; j++)
#pragma unroll
        for (int i = 0; i < 4; i++) acc[j][i] = 0.f;

    for (int kt = 0; kt < 128; kt += 32) {
#pragma unroll
        for (int j = 0; j < 4; j++) {
            int f = tid + j * 256;
            int kk = f >> 5;
            int c4 = f & 31;
            float4 w = __ldg((const float4*)&Wm[(size_t)(kt + kk) * 128 + c4 * 4]);
            uint32_t* p = &Ws[kk * WS_STRIDE + c4 * 4];
            p[0] = f2tf32(w.x); p[1] = f2tf32(w.y); p[2] = f2tf32(w.z); p[3] = f2tf32(w.w);
        }
#pragma unroll
        for (int j = 0; j < 4; j++) {
            int f = tid + j * 256;
            int rr = f >> 3;
            int c4 = f & 7;
            int grow = row0 + rr;
            float4 a = make_float4(0.f, 0.f, 0.f, 0.f);
            if (grow < N) {
                a = __ldg((const float4*)&A[(size_t)grow * 128 + kt + c4 * 4]);
                float nm = __ldg(&norm[grow]);
                a.x *= nm; a.y *= nm; a.z *= nm; a.w *= nm;
            }
            uint32_t* p = &As[rr * AS_STRIDE + c4 * 4];
            p[0] = f2tf32(a.x); p[1] = f2tf32(a.y); p[2] = f2tf32(a.z); p[3] = f2tf32(a.w);
        }
        __syncthreads();

#pragma unroll
        for (int k8 = 0; k8 < 4; k8++) {
            int kb = k8 * 8;
            int r = warp * 16;
            uint32_t a0 = As[(r + g) * AS_STRIDE + kb + t];
            uint32_t a1 = As[(r + g + 8) * AS_STRIDE + kb + t];
            uint32_t a2 = As[(r + g) * AS_STRIDE + kb + t + 4];
            uint32_t a3 = As[(r + g + 8) * AS_STRIDE + kb + t + 4];
#pragma unroll
            for (int j = 0; j < 16; j++) {
                uint32_t b0 = Ws[(kb + t) * WS_STRIDE + j * 8 + g];
                uint32_t b1 = Ws[(kb + t + 4) * WS_STRIDE + j * 8 + g];
                mma_tf32(acc[j], a0, a1, a2, a3, b0, b1);
            }
        }
        __syncthreads();
    }

    const int r1 = row0 + warp * 16 + g;
    const int r2 = r1 + 8;
#pragma unroll
    for (int j = 0; j < 16; j++) {
        int col = j * 8 + 2 * t;
        float2 bv = *(const float2*)&bias[col];
        float2 o1, o2;
        o1.x = fmaxf(acc[j][0] + bv.x, 0.f);
        o1.y = fmaxf(acc[j][1] + bv.y, 0.f);
        o2.x = fmaxf(acc[j][2] + bv.x, 0.f);
        o2.y = fmaxf(acc[j][3] + bv.y, 0.f);
        if (HALF_OUT) {
            if (r1 < N) {
                __half2 h = __floats2half2_rn(o1.x, o1.y);
                *(__half2*)&C16[(size_t)r1 * 128 + col] = h;
            }
            if (r2 < N) {
                __half2 h = __floats2half2_rn(o2.x, o2.y);
                *(__half2*)&C16[(size_t)r2 * 128 + col] = h;
            }
        } else {
            if (r1 < N) *(float2*)&C[(size_t)r1 * 128 + col] = o1;
            if (r2 < N) *(float2*)&C[(size_t)r2 * 128 + col] = o2;
        }
    }
}

extern "C" void kernel_launch(void* const* d_in, const int* in_sizes, int n_in,
                              void* d_out, int out_size) {
    const float* features = (const float*)d_in[0];
    const int* src = (const int*)d_in[1];
    const int* dst = (const int*)d_in[2];
    const float* W1 = (const float*)d_in[3];
    const float* b1 = (const float*)d_in[4];
    const float* W2 = (const float*)d_in[5];
    const float* b2 = (const float*)d_in[6];
    float* out = (float*)d_out;

    int N = in_sizes[0] / D;
    int E = in_sizes[1];

    int *cnt_out, *cnt_in, *row_start, *cursor, *blk_sums, *sorted_src;
    float *nsrc, *ndst, *agg;
    __half* hf16;
    cudaGetSymbolAddress((void**)&cnt_out, g_cnt_out);
    cudaGetSymbolAddress((void**)&cnt_in, g_cnt_in);
    cudaGetSymbolAddress((void**)&row_start, g_row_start);
    cudaGetSymbolAddress((void**)&cursor, g_cursor);
    cudaGetSymbolAddress((void**)&blk_sums, g_blk_sums);
    cudaGetSymbolAddress((void**)&sorted_src, g_sorted_src);
    cudaGetSymbolAddress((void**)&nsrc, g_norm_src);
    cudaGetSymbolAddress((void**)&ndst, g_norm_dst);
    cudaGetSymbolAddress((void**)&agg, g_agg);
    cudaGetSymbolAddress((void**)&hf16, g_hf16);

    const int ZB = 256;
    int nblkN = (N + ZB - 1) / ZB;
    int nblkE = (E + ZB - 1) / ZB;

    // CSR build + norms + fp16 feature mirror
    k_zero2i<<<nblkN, ZB>>>(cnt_out, cnt_in, N);
    k_hist<<<nblkE, ZB>>>(src, dst, cnt_out, cnt_in, E);
    k_f2h<<<(N * D / 4 + ZB - 1) / ZB, ZB>>>(features, hf16, N * D / 4);
    k_scan_block<<<nblkN, SCAN_B>>>(cnt_in, row_start, blk_sums, N);
    k_scan_add_norm<<<nblkN, SCAN_B>>>(row_start, blk_sums, cursor,
                                       cnt_out, cnt_in, nsrc, ndst, nblkN, N);
    k_bucket<<<nblkE, ZB>>>(src, dst, cursor, sorted_src, E);

    int gath_blocks = (N * 32 + ZB - 1) / ZB;
    int gemm_blocks = (N + 127) / 128;

    // layer 1: gather fp16 features -> agg fp32; GEMM -> h (fp16, into hf16)
    k_gather16<<<gath_blocks, ZB>>>(hf16, sorted_src, row_start, cnt_in, nsrc, agg, N);
    k_gemm_tf32<true><<<gemm_blocks, 256>>>(agg, W1, b1, ndst, nullptr, hf16, N);

    // layer 2: gather fp16 h1 -> agg fp32; GEMM -> fp32 out
    k_gather16<<<gath_blocks, ZB>>>(hf16, sorted_src, row_start, cnt_in, nsrc, agg, N);
    k_gemm_tf32<false><<<gemm_blocks, 256>>>(agg, W2, b2, ndst, out, nullptr, N);
}

// round 9
// speedup vs baseline: 1.3779x; 1.0528x over previous
#include <cuda_runtime.h>
#include <cuda_fp16.h>
#include <cstdint>
#include <cstddef>

#define D 128
#define MAXN 50000
#define MAXE 600064
#define SCAN_B 256

// ---- scratch (allocation-free: __device__ globals) ----
__device__ int    g_cnt_out[MAXN];
__device__ int    g_cnt_in[MAXN];
__device__ float  g_norm_src[MAXN];
__device__ float  g_norm_dst[MAXN];
__device__ int    g_row_start[MAXN];
__device__ int    g_cursor[MAXN];
__device__ int    g_blk_sums[SCAN_B];
__device__ int    g_sorted_src[MAXE];
__device__ __half g_hf16[(size_t)MAXN * D];    // fp16 mirror, PRE-SCALED by norm_src
__device__ float  g_agg[(size_t)MAXN * D];     // aggregation buffer (fp32)

__global__ void k_zero2i(int* a, int* b, int n) {
    int i = blockIdx.x * blockDim.x + threadIdx.x;
    if (i < n) { a[i] = 0; b[i] = 0; }
}

__global__ void k_hist(const int* __restrict__ src, const int* __restrict__ dst,
                       int* __restrict__ cnt_out, int* __restrict__ cnt_in, int E) {
    int i = blockIdx.x * blockDim.x + threadIdx.x;
    if (i < E) {
        atomicAdd(&cnt_out[src[i]], 1);
        atomicAdd(&cnt_in[dst[i]], 1);
    }
}

// ---- fp32 features -> fp16 mirror pre-scaled by norm_src; 32 lanes per row ----
__global__ void k_f2h_scaled(const float* __restrict__ in, const float* __restrict__ nsrc,
                             __half* __restrict__ out, int N) {
    int row = (blockIdx.x * blockDim.x + threadIdx.x) >> 5;
    int lane = threadIdx.x & 31;
    if (row >= N) return;
    float ns = __ldg(&nsrc[row]);
    float4 v = __ldg((const float4*)(in + (size_t)row * D) + lane);
    __half2 h0 = __floats2half2_rn(v.x * ns, v.y * ns);
    __half2 h1 = __floats2half2_rn(v.z * ns, v.w * ns);
    uint2 u;
    u.x = *(uint32_t*)&h0;
    u.y = *(uint32_t*)&h1;
    *((uint2*)(out + (size_t)row * D) + lane) = u;
}

// ---- block-level exclusive scan of cnt_in ----
__global__ void k_scan_block(const int* __restrict__ cnt, int* __restrict__ excl,
                             int* __restrict__ blk_sums, int N) {
    __shared__ int sh[SCAN_B];
    int i = blockIdx.x * SCAN_B + threadIdx.x;
    int v = (i < N) ? cnt[i] : 0;
    sh[threadIdx.x] = v; __syncthreads();
#pragma unroll
    for (int off = 1; off < SCAN_B; off <<= 1) {
        int t = (threadIdx.x >= off) ? sh[threadIdx.x - off] : 0;
        __syncthreads();
        sh[threadIdx.x] += t;
        __syncthreads();
    }
    if (i < N) excl[i] = sh[threadIdx.x] - v;
    if (threadIdx.x == SCAN_B - 1) blk_sums[blockIdx.x] = sh[SCAN_B - 1];
}

// ---- finish scan (per-block prefix reduce) + norms ----
__global__ void k_scan_add_norm(int* __restrict__ excl, const int* __restrict__ blk_sums,
                                int* __restrict__ cursor,
                                const int* __restrict__ cnt_out, const int* __restrict__ cnt_in,
                                float* __restrict__ nsrc, float* __restrict__ ndst,
                                int nb, int N) {
    __shared__ int sh[SCAN_B];
    int v = (threadIdx.x < blockIdx.x && threadIdx.x < nb) ? blk_sums[threadIdx.x] : 0;
    sh[threadIdx.x] = v; __syncthreads();
#pragma unroll
    for (int off = 128; off > 0; off >>= 1) {
        if (threadIdx.x < off) sh[threadIdx.x] += sh[threadIdx.x + off];
        __syncthreads();
    }
    int prefix = sh[0];
    int i = blockIdx.x * SCAN_B + threadIdx.x;
    if (i < N) {
        int r = excl[i] + prefix;
        excl[i] = r;
        cursor[i] = r;
        nsrc[i] = rsqrtf(fmaxf((float)cnt_out[i], 1.f));
        ndst[i] = rsqrtf(fmaxf((float)cnt_in[i], 1.f));
    }
}

// ---- bucket edges by dst: CSR src list ----
__global__ void k_bucket(const int* __restrict__ src, const int* __restrict__ dst,
                         int* __restrict__ cursor, int* __restrict__ sorted_src, int E) {
    int i = blockIdx.x * blockDim.x + threadIdx.x;
    if (i < E) {
        int pos = atomicAdd(&cursor[dst[i]], 1);
        sorted_src[pos] = src[i];
    }
}

// ---- add 8 halves (uint4) into 8 fp32 accumulators ----
__device__ __forceinline__ void acc_add8(float* acc, uint4 u) {
    float2 p0 = __half22float2(*(__half2*)&u.x);
    float2 p1 = __half22float2(*(__half2*)&u.y);
    float2 p2 = __half22float2(*(__half2*)&u.z);
    float2 p3 = __half22float2(*(__half2*)&u.w);
    acc[0] += p0.x; acc[1] += p0.y;
    acc[2] += p1.x; acc[3] += p1.y;
    acc[4] += p2.x; acc[5] += p2.y;
    acc[6] += p3.x; acc[7] += p3.y;
}

// ---- atomic-free aggregation: HALF-WARP per dst node, uint4 row loads ----
// hf rows are pre-scaled by norm_src, so inner loop is a pure row sum.
__global__ void k_gather16(const __half* __restrict__ hf, const int* __restrict__ sorted_src,
                           const int* __restrict__ row_start, const int* __restrict__ cnt_in,
                           float* __restrict__ agg, int N) {
    int n = (blockIdx.x * blockDim.x + threadIdx.x) >> 4;
    int lane = threadIdx.x & 15;
    if (n >= N) return;
    int start = __ldg(&row_start[n]);
    int cnt = __ldg(&cnt_in[n]);
    float acc[8] = {0.f, 0.f, 0.f, 0.f, 0.f, 0.f, 0.f, 0.f};
    const int* sp = sorted_src + start;
    int j = 0;
    for (; j + 4 <= cnt; j += 4) {
        int s0 = __ldg(sp + j);
        int s1 = __ldg(sp + j + 1);
        int s2 = __ldg(sp + j + 2);
        int s3 = __ldg(sp + j + 3);
        uint4 u0 = __ldg((const uint4*)(hf + (size_t)s0 * D) + lane);
        uint4 u1 = __ldg((const uint4*)(hf + (size_t)s1 * D) + lane);
        uint4 u2 = __ldg((const uint4*)(hf + (size_t)s2 * D) + lane);
        uint4 u3 = __ldg((const uint4*)(hf + (size_t)s3 * D) + lane);
        acc_add8(acc, u0); acc_add8(acc, u1); acc_add8(acc, u2); acc_add8(acc, u3);
    }
    for (; j < cnt; j++) {
        int s = __ldg(sp + j);
        uint4 u = __ldg((const uint4*)(hf + (size_t)s * D) + lane);
        acc_add8(acc, u);
    }
    float4* ap = (float4*)(agg + (size_t)n * D) + lane * 2;
    ap[0] = make_float4(acc[0], acc[1], acc[2], acc[3]);
    ap[1] = make_float4(acc[4], acc[5], acc[6], acc[7]);
}

// ---- tf32 helpers ----
__device__ __forceinline__ uint32_t f2tf32(float x) {
    uint32_t r;
    asm("cvt.rna.tf32.f32 %0, %1;" : "=r"(r) : "f"(x));
    return r;
}

__device__ __forceinline__ void mma_tf32(float* c, uint32_t a0, uint32_t a1,
                                         uint32_t a2, uint32_t a3,
                                         uint32_t b0, uint32_t b1) {
    asm volatile(
        "mma.sync.aligned.m16n8k8.row.col.f32.tf32.tf32.f32 "
        "{%0,%1,%2,%3}, {%4,%5,%6,%7}, {%8,%9}, {%0,%1,%2,%3};"
        : "+f"(c[0]), "+f"(c[1]), "+f"(c[2]), "+f"(c[3])
        : "r"(a0), "r"(a1), "r"(a2), "r"(a3), "r"(b0), "r"(b1));
}

// ---- fused: C = relu((A * ndst[:,None]) @ W + b) ----
// HALF_OUT: also emit fp16 copy pre-scaled by nsrc (gather operand for next layer).
#define AS_STRIDE 36
#define WS_STRIDE 136

template <bool HALF_OUT>
__global__ __launch_bounds__(256)
void k_gemm_tf32(const float* __restrict__ A, const float* __restrict__ Wm,
                 const float* __restrict__ bias, const float* __restrict__ norm,
                 const float* __restrict__ nsrc,
                 float* __restrict__ C, __half* __restrict__ C16, int N) {
    __shared__ uint32_t As[128 * AS_STRIDE];
    __shared__ uint32_t Ws[32 * WS_STRIDE];

    const int tid = threadIdx.x;
    const int warp = tid >> 5;
    const int lane = tid & 31;
    const int g = lane >> 2;
    const int t = lane & 3;
    const int row0 = blockIdx.x * 128;

    float acc[16][4];
#pragma unroll
    for (int j = 0; j < 16; j++)
#pragma unroll
        for (int i = 0; i < 4; i++) acc[j][i] = 0.f;

    for (int kt = 0; kt < 128; kt += 32) {
#pragma unroll
        for (int j = 0; j < 4; j++) {
            int f = tid + j * 256;
            int kk = f >> 5;
            int c4 = f & 31;
            float4 w = __ldg((const float4*)&Wm[(size_t)(kt + kk) * 128 + c4 * 4]);
            uint32_t* p = &Ws[kk * WS_STRIDE + c4 * 4];
            p[0] = f2tf32(w.x); p[1] = f2tf32(w.y); p[2] = f2tf32(w.z); p[3] = f2tf32(w.w);
        }
#pragma unroll
        for (int j = 0; j < 4; j++) {
            int f = tid + j * 256;
            int rr = f >> 3;
            int c4 = f & 7;
            int grow = row0 + rr;
            float4 a = make_float4(0.f, 0.f, 0.f, 0.f);
            if (grow < N) {
                a = __ldg((const float4*)&A[(size_t)grow * 128 + kt + c4 * 4]);
                float nm = __ldg(&norm[grow]);
                a.x *= nm; a.y *= nm; a.z *= nm; a.w *= nm;
            }
            uint32_t* p = &As[rr * AS_STRIDE + c4 * 4];
            p[0] = f2tf32(a.x); p[1] = f2tf32(a.y); p[2] = f2tf32(a.z); p[3] = f2tf32(a.w);
        }
        __syncthreads();

#pragma unroll
        for (int k8 = 0; k8 < 4; k8++) {
            int kb = k8 * 8;
            int r = warp * 16;
            uint32_t a0 = As[(r + g) * AS_STRIDE + kb + t];
            uint32_t a1 = As[(r + g + 8) * AS_STRIDE + kb + t];
            uint32_t a2 = As[(r + g) * AS_STRIDE + kb + t + 4];
            uint32_t a3 = As[(r + g + 8) * AS_STRIDE + kb + t + 4];
#pragma unroll
            for (int j = 0; j < 16; j++) {
                uint32_t b0 = Ws[(kb + t) * WS_STRIDE + j * 8 + g];
                uint32_t b1 = Ws[(kb + t + 4) * WS_STRIDE + j * 8 + g];
                mma_tf32(acc[j], a0, a1, a2, a3, b0, b1);
            }
        }
        __syncthreads();
    }

    const int r1 = row0 + warp * 16 + g;
    const int r2 = r1 + 8;
    float ns1 = 1.f, ns2 = 1.f;
    if (HALF_OUT) {
        if (r1 < N) ns1 = __ldg(&nsrc[r1]);
        if (r2 < N) ns2 = __ldg(&nsrc[r2]);
    }
#pragma unroll
    for (int j = 0; j < 16; j++) {
        int col = j * 8 + 2 * t;
        float2 bv = *(const float2*)&bias[col];
        float2 o1, o2;
        o1.x = fmaxf(acc[j][0] + bv.x, 0.f);
        o1.y = fmaxf(acc[j][1] + bv.y, 0.f);
        o2.x = fmaxf(acc[j][2] + bv.x, 0.f);
        o2.y = fmaxf(acc[j][3] + bv.y, 0.f);
        if (HALF_OUT) {
            if (r1 < N) {
                __half2 h = __floats2half2_rn(o1.x * ns1, o1.y * ns1);
                *(__half2*)&C16[(size_t)r1 * 128 + col] = h;
            }
            if (r2 < N) {
                __half2 h = __floats2half2_rn(o2.x * ns2, o2.y * ns2);
                *(__half2*)&C16[(size_t)r2 * 128 + col] = h;
            }
        } else {
            if (r1 < N) *(float2*)&C[(size_t)r1 * 128 + col] = o1;
            if (r2 < N) *(float2*)&C[(size_t)r2 * 128 + col] = o2;
        }
    }
}

extern "C" void kernel_launch(void* const* d_in, const int* in_sizes, int n_in,
                              void* d_out, int out_size) {
    const float* features = (const float*)d_in[0];
    const int* src = (const int*)d_in[1];
    const int* dst = (const int*)d_in[2];
    const float* W1 = (const float*)d_in[3];
    const float* b1 = (const float*)d_in[4];
    const float* W2 = (const float*)d_in[5];
    const float* b2 = (const float*)d_in[6];
    float* out = (float*)d_out;

    int N = in_sizes[0] / D;
    int E = in_sizes[1];

    int *cnt_out, *cnt_in, *row_start, *cursor, *blk_sums, *sorted_src;
    float *nsrc, *ndst, *agg;
    __half* hf16;
    cudaGetSymbolAddress((void**)&cnt_out, g_cnt_out);
    cudaGetSymbolAddress((void**)&cnt_in, g_cnt_in);
    cudaGetSymbolAddress((void**)&row_start, g_row_start);
    cudaGetSymbolAddress((void**)&cursor, g_cursor);
    cudaGetSymbolAddress((void**)&blk_sums, g_blk_sums);
    cudaGetSymbolAddress((void**)&sorted_src, g_sorted_src);
    cudaGetSymbolAddress((void**)&nsrc, g_norm_src);
    cudaGetSymbolAddress((void**)&ndst, g_norm_dst);
    cudaGetSymbolAddress((void**)&agg, g_agg);
    cudaGetSymbolAddress((void**)&hf16, g_hf16);

    const int ZB = 256;
    int nblkN = (N + ZB - 1) / ZB;
    int nblkE = (E + ZB - 1) / ZB;

    // CSR build + norms + pre-scaled fp16 feature mirror
    k_zero2i<<<nblkN, ZB>>>(cnt_out, cnt_in, N);
    k_hist<<<nblkE, ZB>>>(src, dst, cnt_out, cnt_in, E);
    k_scan_block<<<nblkN, SCAN_B>>>(cnt_in, row_start, blk_sums, N);
    k_scan_add_norm<<<nblkN, SCAN_B>>>(row_start, blk_sums, cursor,
                                       cnt_out, cnt_in, nsrc, ndst, nblkN, N);
    k_f2h_scaled<<<(N * 32 + ZB - 1) / ZB, ZB>>>(features, nsrc, hf16, N);
    k_bucket<<<nblkE, ZB>>>(src, dst, cursor, sorted_src, E);

    int gath_blocks = (N * 16 + ZB - 1) / ZB;
    int gemm_blocks = (N + 127) / 128;

    // layer 1: sum pre-scaled fp16 rows -> agg; GEMM -> h1 (fp16, pre-scaled by nsrc)
    k_gather16<<<gath_blocks, ZB>>>(hf16, sorted_src, row_start, cnt_in, agg, N);
    k_gemm_tf32<true><<<gemm_blocks, 256>>>(agg, W1, b1, ndst, nsrc, nullptr, hf16, N);

    // layer 2: sum pre-scaled fp16 h1 rows -> agg; GEMM -> fp32 out
    k_gather16<<<gath_blocks, ZB>>>(hf16, sorted_src, row_start, cnt_in, agg, N);
    k_gemm_tf32<false><<<gemm_blocks, 256>>>(agg, W2, b2, ndst, nullptr, out, nullptr, N);
}